// round 1
// baseline (speedup 1.0000x reference)
#include <cuda_runtime.h>

#define N_USERS 50000
#define N_ITEMS 75000
#define N_NODES 125000
#define NNZ     1250000
#define EMB     64
#define N_LAYERS 3
#define BATCH   4096

// Scratch (device globals — allocation-free per harness rules)
__device__ __align__(128) float g_feat[N_NODES * EMB];                 // 32 MB
__device__ __align__(128) float g_agg [N_NODES * EMB];                 // 32 MB
__device__ __align__(128) float g_norm[N_LAYERS * N_NODES * EMB];      // 96 MB

__device__ __forceinline__ float lrelu(float x) {
    return x > 0.0f ? x : 0.2f * x;
}

// ---------------------------------------------------------------------------
// emb -> g_feat  (float4 copy)
__global__ __launch_bounds__(256) void copy_feat_kernel(const float* __restrict__ emb) {
    int i = blockIdx.x * 256 + threadIdx.x;
    if (i < N_NODES * EMB / 4)
        ((float4*)g_feat)[i] = ((const float4*)emb)[i];
}

// ---------------------------------------------------------------------------
// zero g_agg
__global__ __launch_bounds__(256) void zero_agg_kernel() {
    int i = blockIdx.x * 256 + threadIdx.x;
    if (i < N_NODES * EMB / 4)
        ((float4*)g_agg)[i] = make_float4(0.f, 0.f, 0.f, 0.f);
}

// ---------------------------------------------------------------------------
// SpMM: agg[row[e]] += vals[e] * feat[col[e]]
// 16 threads per edge, each handles one float4 (4 dims). Scatter via
// red.global.add.v4.f32 (fire-and-forget 16B reduction to L2).
__global__ __launch_bounds__(256) void spmm_kernel(const int*   __restrict__ row,
                                                   const int*   __restrict__ col,
                                                   const float* __restrict__ vals) {
    int t   = blockIdx.x * 256 + threadIdx.x;
    int e   = t >> 4;
    int seg = t & 15;
    if (e >= NNZ) return;
    int   r = row[e];
    int   c = col[e];
    float v = vals[e];
    float4 f = ((const float4*)g_feat)[c * 16 + seg];
    float4* dst = ((float4*)g_agg) + r * 16 + seg;
    asm volatile("red.global.add.v4.f32 [%0], {%1, %2, %3, %4};"
                 :: "l"(dst), "f"(v * f.x), "f"(v * f.y), "f"(v * f.z), "f"(v * f.w)
                 : "memory");
}

// ---------------------------------------------------------------------------
// Dense per-node update:
//   h1 = lrelu(W1 @ agg + b1); h2 = lrelu(W2 @ (agg*feat) + b2)
//   feat = h1 + h2 ; norm[layer] = feat / max(||feat||, eps)
// Block: 256 threads = 16 nodes x 16 threads; each thread owns 4 output dims.
// Weights transposed into SMEM so LDS.128 reads are conflict-free.
#define FMA4(acc, s, w) { acc.x += (s)*(w).x; acc.y += (s)*(w).y; \
                          acc.z += (s)*(w).z; acc.w += (s)*(w).w; }

__global__ __launch_bounds__(256) void dense_kernel(const float* __restrict__ W1,
                                                    const float* __restrict__ b1,
                                                    const float* __restrict__ W2,
                                                    const float* __restrict__ b2,
                                                    int layer) {
    __shared__ float  w1t[64 * 64];
    __shared__ float  w2t[64 * 64];
    __shared__ float4 sa [16][16];
    __shared__ float4 saf[16][16];
    __shared__ float  sb1[64], sb2[64];

    int t = threadIdx.x;
    const float* W1l = W1 + layer * 64 * 64;
    const float* W2l = W2 + layer * 64 * 64;
    #pragma unroll
    for (int i = t; i < 4096; i += 256) {
        int j = i >> 6, k = i & 63;           // W[j][k] -> Wt[k][j]
        w1t[k * 64 + j] = W1l[i];
        w2t[k * 64 + j] = W2l[i];
    }
    if (t < 64) { sb1[t] = b1[layer * 64 + t]; sb2[t] = b2[layer * 64 + t]; }

    int n    = t >> 4;                 // node within block
    int seg  = t & 15;                 // float4 segment (4 dims)
    int node = blockIdx.x * 16 + n;

    float4 a4 = make_float4(0.f, 0.f, 0.f, 0.f);
    float4 f4 = make_float4(0.f, 0.f, 0.f, 0.f);
    if (node < N_NODES) {
        a4 = ((const float4*)g_agg )[node * 16 + seg];
        f4 = ((const float4*)g_feat)[node * 16 + seg];
    }
    sa [n][seg] = a4;
    saf[n][seg] = make_float4(a4.x * f4.x, a4.y * f4.y, a4.z * f4.z, a4.w * f4.w);
    __syncthreads();

    int j0 = seg * 4;
    float4 acc1 = make_float4(0.f, 0.f, 0.f, 0.f);
    float4 acc2 = make_float4(0.f, 0.f, 0.f, 0.f);
    #pragma unroll
    for (int k4 = 0; k4 < 16; ++k4) {
        float4 av  = sa [n][k4];
        float4 afv = saf[n][k4];
        int kb = k4 * 4;
        float4 w;
        w = *(const float4*)(w1t + (kb + 0) * 64 + j0); FMA4(acc1, av.x,  w);
        w = *(const float4*)(w2t + (kb + 0) * 64 + j0); FMA4(acc2, afv.x, w);
        w = *(const float4*)(w1t + (kb + 1) * 64 + j0); FMA4(acc1, av.y,  w);
        w = *(const float4*)(w2t + (kb + 1) * 64 + j0); FMA4(acc2, afv.y, w);
        w = *(const float4*)(w1t + (kb + 2) * 64 + j0); FMA4(acc1, av.z,  w);
        w = *(const float4*)(w2t + (kb + 2) * 64 + j0); FMA4(acc2, afv.z, w);
        w = *(const float4*)(w1t + (kb + 3) * 64 + j0); FMA4(acc1, av.w,  w);
        w = *(const float4*)(w2t + (kb + 3) * 64 + j0); FMA4(acc2, afv.w, w);
    }

    float4 bb1 = *(const float4*)(sb1 + j0);
    float4 bb2 = *(const float4*)(sb2 + j0);
    float4 o;
    o.x = lrelu(acc1.x + bb1.x) + lrelu(acc2.x + bb2.x);
    o.y = lrelu(acc1.y + bb1.y) + lrelu(acc2.y + bb2.y);
    o.z = lrelu(acc1.z + bb1.z) + lrelu(acc2.z + bb2.z);
    o.w = lrelu(acc1.w + bb1.w) + lrelu(acc2.w + bb2.w);

    // L2 norm over the node's 64 values (16 lanes x 4 each)
    float ss = o.x * o.x + o.y * o.y + o.z * o.z + o.w * o.w;
    #pragma unroll
    for (int off = 8; off; off >>= 1)
        ss += __shfl_xor_sync(0xffffffffu, ss, off);
    float inv = 1.0f / fmaxf(sqrtf(ss), 1e-12f);

    if (node < N_NODES) {
        ((float4*)g_feat)[node * 16 + seg] = o;
        float4 on = make_float4(o.x * inv, o.y * inv, o.z * inv, o.w * inv);
        ((float4*)(g_norm + (size_t)layer * N_NODES * EMB))[node * 16 + seg] = on;
    }
}

// ---------------------------------------------------------------------------
// Final gather: out = [ew[user], ew[N_USERS+pos], ew[N_USERS+neg]],
// ew row = concat(emb, norm0, norm1, norm2), 256 floats = 64 float4.
__global__ __launch_bounds__(256) void gather_kernel(const int* __restrict__ user,
                                                     const int* __restrict__ pos,
                                                     const int* __restrict__ neg,
                                                     const float* __restrict__ emb,
                                                     float* __restrict__ out) {
    int o4 = blockIdx.x * 256 + threadIdx.x;      // float4 index into out
    if (o4 >= 3 * BATCH * 64) return;
    int c4 = o4 & 63;                              // which float4 within row
    int rr = o4 >> 6;                              // 0 .. 3*BATCH-1
    int tsel = rr / BATCH;
    int r    = rr - tsel * BATCH;
    int node = (tsel == 0) ? user[r]
             : (tsel == 1) ? (N_USERS + pos[r])
                           : (N_USERS + neg[r]);
    int part = c4 >> 4;                            // 0=emb, 1..3=norm layers
    int cc   = c4 & 15;
    float4 v;
    if (part == 0)
        v = ((const float4*)emb)[node * 16 + cc];
    else
        v = ((const float4*)(g_norm + (size_t)(part - 1) * N_NODES * EMB))[node * 16 + cc];
    ((float4*)out)[o4] = v;
}

// ---------------------------------------------------------------------------
extern "C" void kernel_launch(void* const* d_in, const int* in_sizes, int n_in,
                              void* d_out, int out_size) {
    const int*   user = (const int*)  d_in[0];
    const int*   pos  = (const int*)  d_in[1];
    const int*   neg  = (const int*)  d_in[2];
    const int*   row  = (const int*)  d_in[3];
    const int*   col  = (const int*)  d_in[4];
    const float* vals = (const float*)d_in[5];
    const float* emb  = (const float*)d_in[6];
    const float* W1   = (const float*)d_in[7];
    const float* b1   = (const float*)d_in[8];
    const float* W2   = (const float*)d_in[9];
    const float* b2   = (const float*)d_in[10];
    float* out = (float*)d_out;

    const int VEC_BLOCKS  = (N_NODES * EMB / 4 + 255) / 256;   // 7813
    const int SPMM_BLOCKS = (NNZ * 16 + 255) / 256;            // 78125
    const int NODE_BLOCKS = (N_NODES + 15) / 16;               // 7813

    copy_feat_kernel<<<VEC_BLOCKS, 256>>>(emb);
    for (int l = 0; l < N_LAYERS; ++l) {
        zero_agg_kernel<<<VEC_BLOCKS, 256>>>();
        spmm_kernel<<<SPMM_BLOCKS, 256>>>(row, col, vals);
        dense_kernel<<<NODE_BLOCKS, 256>>>(W1, b1, W2, b2, l);
    }
    gather_kernel<<<(3 * BATCH * 64 + 255) / 256, 256>>>(user, pos, neg, emb, out);
}

// round 2
// speedup vs baseline: 3.1047x; 3.1047x over previous
#include <cuda_runtime.h>

#define N_USERS 50000
#define N_ITEMS 75000
#define N_NODES 125000
#define NNZ     1250000
#define EMB     64
#define N_LAYERS 3
#define BATCH   4096

// Scratch (device globals — allocation-free per harness rules)
__device__ __align__(128) float g_feat[N_NODES * EMB];                 // 32 MB
__device__ __align__(128) float g_agg [N_NODES * EMB];                 // 32 MB
__device__ __align__(128) float g_norm[N_LAYERS * N_NODES * EMB];      // 96 MB

__device__ __forceinline__ float lrelu(float x) {
    return x > 0.0f ? x : 0.2f * x;
}

// Packed fp32x2 FMA (sm_103a FFMA2) — acc = a*b + acc on both 32-bit halves
#define FMA2(acc, a, b) \
    asm("fma.rn.f32x2 %0, %1, %2, %0;" : "+l"(acc) : "l"(a), "l"(b))
#define PACK2(d, s) \
    asm("mov.b64 %0, {%1, %1};" : "=l"(d) : "f"(s))

__device__ __forceinline__ float lo2(unsigned long long v) {
    return __uint_as_float((unsigned)v);
}
__device__ __forceinline__ float hi2(unsigned long long v) {
    return __uint_as_float((unsigned)(v >> 32));
}

// ---------------------------------------------------------------------------
__global__ __launch_bounds__(256) void copy_feat_kernel(const float* __restrict__ emb) {
    int i = blockIdx.x * 256 + threadIdx.x;
    if (i < N_NODES * EMB / 4)
        ((float4*)g_feat)[i] = ((const float4*)emb)[i];
}

__global__ __launch_bounds__(256) void zero_agg_kernel() {
    int i = blockIdx.x * 256 + threadIdx.x;
    if (i < N_NODES * EMB / 4)
        ((float4*)g_agg)[i] = make_float4(0.f, 0.f, 0.f, 0.f);
}

// ---------------------------------------------------------------------------
// SpMM: agg[row[e]] += vals[e] * feat[col[e]]  (red.global.add.v4.f32 scatter)
__global__ __launch_bounds__(256) void spmm_kernel(const int*   __restrict__ row,
                                                   const int*   __restrict__ col,
                                                   const float* __restrict__ vals) {
    int t   = blockIdx.x * 256 + threadIdx.x;
    int e   = t >> 4;
    int seg = t & 15;
    if (e >= NNZ) return;
    int   r = row[e];
    int   c = col[e];
    float v = vals[e];
    float4 f = ((const float4*)g_feat)[c * 16 + seg];
    float4* dst = ((float4*)g_agg) + r * 16 + seg;
    asm volatile("red.global.add.v4.f32 [%0], {%1, %2, %3, %4};"
                 :: "l"(dst), "f"(v * f.x), "f"(v * f.y), "f"(v * f.z), "f"(v * f.w)
                 : "memory");
}

// ---------------------------------------------------------------------------
// Dense per-node update, register-blocked 2xGEMM with packed f32x2 FMA.
//   h1 = lrelu(W1 @ agg + b1); h2 = lrelu(W2 @ (agg*feat) + b2)
//   feat = h1 + h2 ; norm[layer] = feat / max(||feat||, eps)
// Block: 256 threads -> tile of 128 nodes x 64 outputs.
//   tx = t&15 -> 4 output dims (j0 = tx*4)
//   ty = t>>4 -> 8 nodes (4 node-pairs, f32x2-packed)
// SMEM: A and A*F pair-interleaved [pair][k][2] (stride 130 floats/pair),
//       W1T/W2T transposed [k][j] (stride 68 floats/row).
#define M_TILE      128
#define PAIR_STRIDE 130         // 64 k * 2 + 2 pad (floats per node-pair)
#define W_STRIDE    68          // 64 + 4 pad
#define SA_FLOATS   (64 * PAIR_STRIDE)            // 8320
#define SW_FLOATS   (64 * W_STRIDE)               // 4352
#define DENSE_SMEM  ((2 * SA_FLOATS + 2 * SW_FLOATS) * 4)   // 101376 B

__global__ __launch_bounds__(256, 2) void dense_kernel(const float* __restrict__ W1,
                                                       const float* __restrict__ b1,
                                                       const float* __restrict__ W2,
                                                       const float* __restrict__ b2,
                                                       int layer) {
    extern __shared__ float smem[];
    float* sA  = smem;                       // [64 pairs][64 k][2]
    float* sAF = sA  + SA_FLOATS;
    float* sW1 = sAF + SA_FLOATS;            // [64 k][64 j] padded
    float* sW2 = sW1 + SW_FLOATS;

    const int t    = threadIdx.x;
    const int tx   = t & 15;
    const int ty   = t >> 4;
    const int j0   = tx * 4;
    const int base = blockIdx.x * M_TILE;

    // Stage weights (transposed) -------------------------------------------
    const float* W1l = W1 + layer * 4096;
    const float* W2l = W2 + layer * 4096;
    #pragma unroll
    for (int i = t; i < 4096; i += 256) {
        int j = i >> 6, k = i & 63;
        sW1[k * W_STRIDE + j] = W1l[i];
        sW2[k * W_STRIDE + j] = W2l[i];
    }

    // Stage A = agg and AF = agg*feat, pair-interleaved --------------------
    #pragma unroll
    for (int idx = t; idx < M_TILE * 16; idx += 256) {
        int mm   = idx >> 4;
        int seg  = idx & 15;
        int node = base + mm;
        float4 a4 = make_float4(0.f, 0.f, 0.f, 0.f);
        float4 f4 = make_float4(0.f, 0.f, 0.f, 0.f);
        if (node < N_NODES) {
            a4 = ((const float4*)g_agg )[node * 16 + seg];
            f4 = ((const float4*)g_feat)[node * 16 + seg];
        }
        int pbase = (mm >> 1) * PAIR_STRIDE + (mm & 1);
        #pragma unroll
        for (int i = 0; i < 4; ++i) {
            float av = (&a4.x)[i];
            float fv = (&f4.x)[i];
            int off = pbase + (seg * 4 + i) * 2;
            sA [off] = av;
            sAF[off] = av * fv;
        }
    }
    __syncthreads();

    // Main loop ------------------------------------------------------------
    unsigned long long acc1[16], acc2[16];   // [j*4 + mp]
    #pragma unroll
    for (int i = 0; i < 16; ++i) { acc1[i] = 0ull; acc2[i] = 0ull; }

    const int p0 = ty * 4;                   // first node-pair of this thread

    #pragma unroll 8
    for (int k = 0; k < 64; ++k) {
        unsigned long long A2[4], AF2[4];
        #pragma unroll
        for (int mp = 0; mp < 4; ++mp) {
            A2 [mp] = *(const unsigned long long*)(sA  + (p0 + mp) * PAIR_STRIDE + 2 * k);
            AF2[mp] = *(const unsigned long long*)(sAF + (p0 + mp) * PAIR_STRIDE + 2 * k);
        }
        float4 w1 = *(const float4*)(sW1 + k * W_STRIDE + j0);
        float4 w2 = *(const float4*)(sW2 + k * W_STRIDE + j0);
        #pragma unroll
        for (int j = 0; j < 4; ++j) {
            unsigned long long wd1, wd2;
            PACK2(wd1, (&w1.x)[j]);
            PACK2(wd2, (&w2.x)[j]);
            #pragma unroll
            for (int mp = 0; mp < 4; ++mp) {
                FMA2(acc1[j * 4 + mp], A2[mp],  wd1);
                FMA2(acc2[j * 4 + mp], AF2[mp], wd2);
            }
        }
    }

    // Epilogue: bias + lrelu + sum, L2 norm over 64 dims (reduce across 16 tx)
    float bb1[4], bb2[4];
    #pragma unroll
    for (int j = 0; j < 4; ++j) {
        bb1[j] = __ldg(b1 + layer * 64 + j0 + j);
        bb2[j] = __ldg(b2 + layer * 64 + j0 + j);
    }

    float* normL = g_norm + (size_t)layer * N_NODES * EMB;

    #pragma unroll
    for (int mp = 0; mp < 4; ++mp) {
        #pragma unroll
        for (int h = 0; h < 2; ++h) {
            float o[4];
            #pragma unroll
            for (int j = 0; j < 4; ++j) {
                unsigned long long v1 = acc1[j * 4 + mp];
                unsigned long long v2 = acc2[j * 4 + mp];
                float a1 = (h ? hi2(v1) : lo2(v1)) + bb1[j];
                float a2 = (h ? hi2(v2) : lo2(v2)) + bb2[j];
                o[j] = lrelu(a1) + lrelu(a2);
            }
            float ss = o[0]*o[0] + o[1]*o[1] + o[2]*o[2] + o[3]*o[3];
            #pragma unroll
            for (int off = 8; off; off >>= 1)
                ss += __shfl_xor_sync(0xffffffffu, ss, off);
            float inv = __fdividef(1.0f, fmaxf(sqrtf(ss), 1e-12f));

            int node = base + ty * 8 + mp * 2 + h;
            if (node < N_NODES) {
                float4 ov = make_float4(o[0], o[1], o[2], o[3]);
                ((float4*)g_feat)[node * 16 + tx] = ov;
                float4 on = make_float4(o[0]*inv, o[1]*inv, o[2]*inv, o[3]*inv);
                ((float4*)normL)[node * 16 + tx] = on;
            }
        }
    }
}

// ---------------------------------------------------------------------------
// Final gather: out = [ew[user], ew[N_USERS+pos], ew[N_USERS+neg]],
// ew row = concat(emb, norm0, norm1, norm2), 256 floats = 64 float4.
__global__ __launch_bounds__(256) void gather_kernel(const int* __restrict__ user,
                                                     const int* __restrict__ pos,
                                                     const int* __restrict__ neg,
                                                     const float* __restrict__ emb,
                                                     float* __restrict__ out) {
    int o4 = blockIdx.x * 256 + threadIdx.x;
    if (o4 >= 3 * BATCH * 64) return;
    int c4 = o4 & 63;
    int rr = o4 >> 6;
    int tsel = rr / BATCH;
    int r    = rr - tsel * BATCH;
    int node = (tsel == 0) ? user[r]
             : (tsel == 1) ? (N_USERS + pos[r])
                           : (N_USERS + neg[r]);
    int part = c4 >> 4;
    int cc   = c4 & 15;
    float4 v;
    if (part == 0)
        v = ((const float4*)emb)[node * 16 + cc];
    else
        v = ((const float4*)(g_norm + (size_t)(part - 1) * N_NODES * EMB))[node * 16 + cc];
    ((float4*)out)[o4] = v;
}

// ---------------------------------------------------------------------------
extern "C" void kernel_launch(void* const* d_in, const int* in_sizes, int n_in,
                              void* d_out, int out_size) {
    const int*   user = (const int*)  d_in[0];
    const int*   pos  = (const int*)  d_in[1];
    const int*   neg  = (const int*)  d_in[2];
    const int*   row  = (const int*)  d_in[3];
    const int*   col  = (const int*)  d_in[4];
    const float* vals = (const float*)d_in[5];
    const float* emb  = (const float*)d_in[6];
    const float* W1   = (const float*)d_in[7];
    const float* b1   = (const float*)d_in[8];
    const float* W2   = (const float*)d_in[9];
    const float* b2   = (const float*)d_in[10];
    float* out = (float*)d_out;

    static bool attr_set = false;
    if (!attr_set) {
        cudaFuncSetAttribute(dense_kernel,
                             cudaFuncAttributeMaxDynamicSharedMemorySize, DENSE_SMEM);
        attr_set = true;
    }

    const int VEC_BLOCKS   = (N_NODES * EMB / 4 + 255) / 256;   // 7813
    const int SPMM_BLOCKS  = (NNZ * 16 + 255) / 256;            // 78125
    const int DENSE_BLOCKS = (N_NODES + M_TILE - 1) / M_TILE;   // 977

    copy_feat_kernel<<<VEC_BLOCKS, 256>>>(emb);
    for (int l = 0; l < N_LAYERS; ++l) {
        zero_agg_kernel<<<VEC_BLOCKS, 256>>>();
        spmm_kernel<<<SPMM_BLOCKS, 256>>>(row, col, vals);
        dense_kernel<<<DENSE_BLOCKS, 256, DENSE_SMEM>>>(W1, b1, W2, b2, l);
    }
    gather_kernel<<<(3 * BATCH * 64 + 255) / 256, 256>>>(user, pos, neg, emb, out);
}

// round 4
// speedup vs baseline: 4.2049x; 1.3544x over previous
#include <cuda_runtime.h>

#define N_USERS 50000
#define N_ITEMS 75000
#define N_NODES 125000
#define NNZ     1250000
#define EMB     64
#define N_LAYERS 3
#define BATCH   4096
#define SCAN_BLOCKS 489        // ceil(125000/256)

// Scratch (device globals — allocation-free per harness rules)
__device__ __align__(128) float g_feat[N_NODES * EMB];                 // 32 MB
__device__ __align__(128) float g_agg [N_NODES * EMB];                 // 32 MB
__device__ __align__(128) float g_norm[N_LAYERS * N_NODES * EMB];      // 96 MB
// CSR scratch
__device__ __align__(128) int   g_cnt   [N_NODES];
__device__ __align__(128) int   g_rowptr[N_NODES + 1];
__device__ __align__(128) int   g_cursor[N_NODES];
__device__ __align__(128) int   g_bsum  [512];
__device__ __align__(128) int   g_boff  [512];
__device__ __align__(128) int   g_cols  [NNZ];
__device__ __align__(128) float g_vals  [NNZ];

__device__ __forceinline__ float lrelu(float x) {
    return x > 0.0f ? x : 0.2f * x;
}

// Packed fp32x2 FMA (sm_103a FFMA2)
#define FMA2(acc, a, b) \
    asm("fma.rn.f32x2 %0, %1, %2, %0;" : "+l"(acc) : "l"(a), "l"(b))
#define PACK2(d, s) \
    asm("mov.b64 %0, {%1, %1};" : "=l"(d) : "f"(s))

__device__ __forceinline__ float lo2(unsigned long long v) {
    return __uint_as_float((unsigned)v);
}
__device__ __forceinline__ float hi2(unsigned long long v) {
    return __uint_as_float((unsigned)(v >> 32));
}

// ---------------------------------------------------------------------------
// copy emb -> g_feat, and zero the CSR histogram
__global__ __launch_bounds__(256) void copy_feat_kernel(const float* __restrict__ emb) {
    int i = blockIdx.x * 256 + threadIdx.x;
    if (i < N_NODES * EMB / 4)
        ((float4*)g_feat)[i] = ((const float4*)emb)[i];
    if (i < N_NODES) g_cnt[i] = 0;
}

// ---------------------------------------------------------------------------
// CSR build
__global__ __launch_bounds__(256) void hist_kernel(const int* __restrict__ row) {
    int e = blockIdx.x * 256 + threadIdx.x;
    if (e < NNZ) atomicAdd(&g_cnt[row[e]], 1);
}

// per-block exclusive scan of g_cnt; raw exclusive -> g_rowptr, totals -> g_bsum
__global__ __launch_bounds__(256) void scan1_kernel() {
    __shared__ int s[256];
    int tid = threadIdx.x;
    int i   = blockIdx.x * 256 + tid;
    int x   = (i < N_NODES) ? g_cnt[i] : 0;
    s[tid] = x;
    __syncthreads();
    #pragma unroll
    for (int off = 1; off < 256; off <<= 1) {
        int v = (tid >= off) ? s[tid - off] : 0;
        __syncthreads();
        s[tid] += v;
        __syncthreads();
    }
    if (i < N_NODES) g_rowptr[i] = s[tid] - x;     // exclusive within block
    if (tid == 255) g_bsum[blockIdx.x] = s[255];
}

// single block: exclusive scan of block sums
__global__ __launch_bounds__(512) void scan2_kernel() {
    __shared__ int s[512];
    int tid = threadIdx.x;
    int x = (tid < SCAN_BLOCKS) ? g_bsum[tid] : 0;
    s[tid] = x;
    __syncthreads();
    #pragma unroll
    for (int off = 1; off < 512; off <<= 1) {
        int v = (tid >= off) ? s[tid - off] : 0;
        __syncthreads();
        s[tid] += v;
        __syncthreads();
    }
    g_boff[tid] = s[tid] - x;
}

// apply block offsets; init cursor; set sentinel
__global__ __launch_bounds__(256) void scan3_kernel() {
    int i = blockIdx.x * 256 + threadIdx.x;
    if (i < N_NODES) {
        int v = g_rowptr[i] + g_boff[blockIdx.x];
        g_rowptr[i] = v;
        g_cursor[i] = v;
    }
    if (i == 0) g_rowptr[N_NODES] = NNZ;
}

// scatter edges into row-sorted order
__global__ __launch_bounds__(256) void scatter_kernel(const int*   __restrict__ row,
                                                      const int*   __restrict__ col,
                                                      const float* __restrict__ vals) {
    int e = blockIdx.x * 256 + threadIdx.x;
    if (e >= NNZ) return;
    int pos = atomicAdd(&g_cursor[row[e]], 1);
    g_cols[pos] = col[e];
    g_vals[pos] = vals[e];
}

// ---------------------------------------------------------------------------
// Gather-SpMM over CSR: agg[r] = sum_j val[j] * feat[col[j]]
// 16 threads per row, each owns one float4; 2-edge unroll for MLP.
__global__ __launch_bounds__(256) void spmm_csr_kernel() {
    int t   = blockIdx.x * 256 + threadIdx.x;
    int r   = t >> 4;
    int seg = t & 15;
    if (r >= N_NODES) return;
    int j  = g_rowptr[r];
    int s1 = g_rowptr[r + 1];
    float4 acc = make_float4(0.f, 0.f, 0.f, 0.f);
    const float4* feat4 = (const float4*)g_feat;
    for (; j + 1 < s1; j += 2) {
        int   c0 = __ldg(g_cols + j);
        float v0 = __ldg(g_vals + j);
        int   c1 = __ldg(g_cols + j + 1);
        float v1 = __ldg(g_vals + j + 1);
        float4 f0 = __ldg(feat4 + c0 * 16 + seg);
        float4 f1 = __ldg(feat4 + c1 * 16 + seg);
        acc.x += v0 * f0.x + v1 * f1.x;
        acc.y += v0 * f0.y + v1 * f1.y;
        acc.z += v0 * f0.z + v1 * f1.z;
        acc.w += v0 * f0.w + v1 * f1.w;
    }
    if (j < s1) {
        int   c0 = __ldg(g_cols + j);
        float v0 = __ldg(g_vals + j);
        float4 f0 = __ldg(feat4 + c0 * 16 + seg);
        acc.x += v0 * f0.x;
        acc.y += v0 * f0.y;
        acc.z += v0 * f0.z;
        acc.w += v0 * f0.w;
    }
    ((float4*)g_agg)[r * 16 + seg] = acc;
}

// ---------------------------------------------------------------------------
// Dense per-node update, register-blocked 2xGEMM with packed f32x2 FMA.
#define M_TILE      128
#define PAIR_STRIDE 130
#define W_STRIDE    68
#define SA_FLOATS   (64 * PAIR_STRIDE)
#define SW_FLOATS   (64 * W_STRIDE)
#define DENSE_SMEM  ((2 * SA_FLOATS + 2 * SW_FLOATS) * 4)

__global__ __launch_bounds__(256, 2) void dense_kernel(const float* __restrict__ W1,
                                                       const float* __restrict__ b1,
                                                       const float* __restrict__ W2,
                                                       const float* __restrict__ b2,
                                                       int layer) {
    extern __shared__ float smem[];
    float* sA  = smem;
    float* sAF = sA  + SA_FLOATS;
    float* sW1 = sAF + SA_FLOATS;
    float* sW2 = sW1 + SW_FLOATS;

    const int t    = threadIdx.x;
    const int tx   = t & 15;
    const int ty   = t >> 4;
    const int j0   = tx * 4;
    const int base = blockIdx.x * M_TILE;

    const float* W1l = W1 + layer * 4096;
    const float* W2l = W2 + layer * 4096;
    #pragma unroll
    for (int i = t; i < 4096; i += 256) {
        int j = i >> 6, k = i & 63;
        sW1[k * W_STRIDE + j] = W1l[i];
        sW2[k * W_STRIDE + j] = W2l[i];
    }

    #pragma unroll
    for (int idx = t; idx < M_TILE * 16; idx += 256) {
        int mm   = idx >> 4;
        int seg  = idx & 15;
        int node = base + mm;
        float4 a4 = make_float4(0.f, 0.f, 0.f, 0.f);
        float4 f4 = make_float4(0.f, 0.f, 0.f, 0.f);
        if (node < N_NODES) {
            a4 = ((const float4*)g_agg )[node * 16 + seg];
            f4 = ((const float4*)g_feat)[node * 16 + seg];
        }
        int pbase = (mm >> 1) * PAIR_STRIDE + (mm & 1);
        #pragma unroll
        for (int i = 0; i < 4; ++i) {
            float av = (&a4.x)[i];
            float fv = (&f4.x)[i];
            int off = pbase + (seg * 4 + i) * 2;
            sA [off] = av;
            sAF[off] = av * fv;
        }
    }
    __syncthreads();

    unsigned long long acc1[16], acc2[16];
    #pragma unroll
    for (int i = 0; i < 16; ++i) { acc1[i] = 0ull; acc2[i] = 0ull; }

    const int p0 = ty * 4;

    #pragma unroll 8
    for (int k = 0; k < 64; ++k) {
        unsigned long long A2[4], AF2[4];
        #pragma unroll
        for (int mp = 0; mp < 4; ++mp) {
            A2 [mp] = *(const unsigned long long*)(sA  + (p0 + mp) * PAIR_STRIDE + 2 * k);
            AF2[mp] = *(const unsigned long long*)(sAF + (p0 + mp) * PAIR_STRIDE + 2 * k);
        }
        float4 w1 = *(const float4*)(sW1 + k * W_STRIDE + j0);
        float4 w2 = *(const float4*)(sW2 + k * W_STRIDE + j0);
        #pragma unroll
        for (int j = 0; j < 4; ++j) {
            unsigned long long wd1, wd2;
            PACK2(wd1, (&w1.x)[j]);
            PACK2(wd2, (&w2.x)[j]);
            #pragma unroll
            for (int mp = 0; mp < 4; ++mp) {
                FMA2(acc1[j * 4 + mp], A2[mp],  wd1);
                FMA2(acc2[j * 4 + mp], AF2[mp], wd2);
            }
        }
    }

    float bb1[4], bb2[4];
    #pragma unroll
    for (int j = 0; j < 4; ++j) {
        bb1[j] = __ldg(b1 + layer * 64 + j0 + j);
        bb2[j] = __ldg(b2 + layer * 64 + j0 + j);
    }

    float* normL = g_norm + (size_t)layer * N_NODES * EMB;

    #pragma unroll
    for (int mp = 0; mp < 4; ++mp) {
        #pragma unroll
        for (int h = 0; h < 2; ++h) {
            float o[4];
            #pragma unroll
            for (int j = 0; j < 4; ++j) {
                unsigned long long v1 = acc1[j * 4 + mp];
                unsigned long long v2 = acc2[j * 4 + mp];
                float a1 = (h ? hi2(v1) : lo2(v1)) + bb1[j];
                float a2 = (h ? hi2(v2) : lo2(v2)) + bb2[j];
                o[j] = lrelu(a1) + lrelu(a2);
            }
            float ss = o[0]*o[0] + o[1]*o[1] + o[2]*o[2] + o[3]*o[3];
            #pragma unroll
            for (int off = 8; off; off >>= 1)
                ss += __shfl_xor_sync(0xffffffffu, ss, off);
            float inv = __fdividef(1.0f, fmaxf(sqrtf(ss), 1e-12f));

            int node = base + ty * 8 + mp * 2 + h;
            if (node < N_NODES) {
                float4 ov = make_float4(o[0], o[1], o[2], o[3]);
                ((float4*)g_feat)[node * 16 + tx] = ov;
                float4 on = make_float4(o[0]*inv, o[1]*inv, o[2]*inv, o[3]*inv);
                ((float4*)normL)[node * 16 + tx] = on;
            }
        }
    }
}

// ---------------------------------------------------------------------------
// Final gather
__global__ __launch_bounds__(256) void gather_kernel(const int* __restrict__ user,
                                                     const int* __restrict__ pos,
                                                     const int* __restrict__ neg,
                                                     const float* __restrict__ emb,
                                                     float* __restrict__ out) {
    int o4 = blockIdx.x * 256 + threadIdx.x;
    if (o4 >= 3 * BATCH * 64) return;
    int c4 = o4 & 63;
    int rr = o4 >> 6;
    int tsel = rr / BATCH;
    int r    = rr - tsel * BATCH;
    int node = (tsel == 0) ? user[r]
             : (tsel == 1) ? (N_USERS + pos[r])
                           : (N_USERS + neg[r]);
    int part = c4 >> 4;
    int cc   = c4 & 15;
    float4 v;
    if (part == 0)
        v = ((const float4*)emb)[node * 16 + cc];
    else
        v = ((const float4*)(g_norm + (size_t)(part - 1) * N_NODES * EMB))[node * 16 + cc];
    ((float4*)out)[o4] = v;
}

// ---------------------------------------------------------------------------
extern "C" void kernel_launch(void* const* d_in, const int* in_sizes, int n_in,
                              void* d_out, int out_size) {
    const int*   user = (const int*)  d_in[0];
    const int*   pos  = (const int*)  d_in[1];
    const int*   neg  = (const int*)  d_in[2];
    const int*   row  = (const int*)  d_in[3];
    const int*   col  = (const int*)  d_in[4];
    const float* vals = (const float*)d_in[5];
    const float* emb  = (const float*)d_in[6];
    const float* W1   = (const float*)d_in[7];
    const float* b1   = (const float*)d_in[8];
    const float* W2   = (const float*)d_in[9];
    const float* b2   = (const float*)d_in[10];
    float* out = (float*)d_out;

    static bool attr_set = false;
    if (!attr_set) {
        cudaFuncSetAttribute(dense_kernel,
                             cudaFuncAttributeMaxDynamicSharedMemorySize, DENSE_SMEM);
        attr_set = true;
    }

    const int VEC_BLOCKS   = (N_NODES * EMB / 4 + 255) / 256;   // 7813
    const int EDGE_BLOCKS  = (NNZ + 255) / 256;                 // 4883
    const int ROW16_BLOCKS = (N_NODES * 16 + 255) / 256;        // 7813
    const int DENSE_BLOCKS = (N_NODES + M_TILE - 1) / M_TILE;   // 977

    copy_feat_kernel<<<VEC_BLOCKS, 256>>>(emb);
    hist_kernel<<<EDGE_BLOCKS, 256>>>(row);
    scan1_kernel<<<SCAN_BLOCKS, 256>>>();
    scan2_kernel<<<1, 512>>>();
    scan3_kernel<<<SCAN_BLOCKS, 256>>>();
    scatter_kernel<<<EDGE_BLOCKS, 256>>>(row, col, vals);

    for (int l = 0; l < N_LAYERS; ++l) {
        spmm_csr_kernel<<<ROW16_BLOCKS, 256>>>();
        dense_kernel<<<DENSE_BLOCKS, 256, DENSE_SMEM>>>(W1, b1, W2, b2, l);
    }
    gather_kernel<<<(3 * BATCH * 64 + 255) / 256, 256>>>(user, pos, neg, emb, out);
}